// round 4
// baseline (speedup 1.0000x reference)
#include <cuda_runtime.h>
#include <cstdint>

#define S_LEN 256
#define BATCH 64
#define HID   1024
#define G4    4096
#define RGRID 128

// ---------------- device scratch (no runtime allocation allowed) ------------
__device__ float    g_xz[(size_t)S_LEN * G4 * BATCH];  // 256 MB, layout [s][n][b]
__device__ unsigned g_hT[2][HID*BATCH];                // h transposed [k=j][b], tf32, SW128-swizzled
__device__ unsigned g_bar;                             // monotonic grid barrier

// ---------------- helpers ----------------------------------------------------
__device__ __forceinline__ unsigned f2tf(float x){
  unsigned u; asm("cvt.rna.tf32.f32 %0, %1;" : "=r"(u) : "f"(x)); return u;
}
__device__ __forceinline__ void mma8(float* d, const unsigned* a, unsigned b0, unsigned b1){
  asm volatile("mma.sync.aligned.m16n8k8.row.col.f32.tf32.tf32.f32 "
      "{%0,%1,%2,%3},{%4,%5,%6,%7},{%8,%9},{%0,%1,%2,%3};"
      : "+f"(d[0]),"+f"(d[1]),"+f"(d[2]),"+f"(d[3])
      : "r"(a[0]),"r"(a[1]),"r"(a[2]),"r"(a[3]),"r"(b0),"r"(b1));
}
__device__ __forceinline__ unsigned ld_acq(const unsigned* p){
  unsigned v; asm volatile("ld.acquire.gpu.global.u32 %0, [%1];" : "=r"(v) : "l"(p)); return v;
}
// swizzled word index inside the [k][b] h buffer (matches SW128 on 4B words)
__device__ __forceinline__ unsigned hswz(unsigned k, unsigned b){
  return k*64u + (b ^ (((k&3u)<<3) | (((b>>5)&1u)<<2)));
}
__device__ __forceinline__ void mbar_init(unsigned mbar, unsigned cnt){
  asm volatile("mbarrier.init.shared.b64 [%0], %1;" :: "r"(mbar), "r"(cnt) : "memory");
}
__device__ __forceinline__ void mbar_expect_tx(unsigned mbar, unsigned bytes){
  asm volatile("mbarrier.arrive.expect_tx.shared.b64 _, [%0], %1;" :: "r"(mbar), "r"(bytes) : "memory");
}
__device__ __forceinline__ void bulk_g2s(unsigned dst, const void* src, unsigned bytes, unsigned mbar){
  asm volatile("cp.async.bulk.shared::cta.global.mbarrier::complete_tx::bytes [%0], [%1], %2, [%3];"
      :: "r"(dst), "l"(src), "r"(bytes), "r"(mbar) : "memory");
}
__device__ __forceinline__ void mbar_wait(unsigned mbar, unsigned parity){
  asm volatile("{\n\t.reg .pred P;\n\t"
    "WL_%=:\n\t"
    "mbarrier.try_wait.parity.acquire.cta.shared::cta.b64 P, [%0], %1, 0x989680;\n\t"
    "@!P bra WL_%=;\n\t}" :: "r"(mbar), "r"(parity) : "memory");
}

// ---------------- phase 1: xz = x @ Wx^T + b  (tf32 mma GEMM) + fused init ---
__global__ void __launch_bounds__(256,2) gemm_xz_kernel(
    const float* __restrict__ x, const float* __restrict__ h0,
    const float* __restrict__ Wf, const float* __restrict__ Wi,
    const float* __restrict__ Wg, const float* __restrict__ Wo,
    const float* __restrict__ bfp, const float* __restrict__ bip,
    const float* __restrict__ bgp, const float* __restrict__ bop)
{
  // fused init: block (0,0) resets barrier and writes h0 (tf32, swizzled [k][b])
  if (blockIdx.x==0 && blockIdx.y==0) {
    if (threadIdx.x==0) g_bar = 0;
    for (int i = threadIdx.x; i < BATCH*HID; i += 256) {
      int b = i >> 10, j = i & 1023;
      g_hT[0][hswz(j, b)] = f2tf(h0[i]);
    }
  }

  __shared__ unsigned a_s[128][36];
  __shared__ unsigned b_s[128][36];
  const int m0 = blockIdx.y*128, n0 = blockIdx.x*128;
  const int tid = threadIdx.x, wid = tid>>5, lane = tid&31;
  const int wm = wid&3, wn = wid>>2, gid = lane>>2, tig = lane&3;
  const int gate = n0 >> 10;
  const float* Wp = (gate==0)?Wf:(gate==1)?Wi:(gate==2)?Wg:Wo;
  const float* bp = (gate==0)?bfp:(gate==1)?bip:(gate==2)?bgp:bop;

  float acc[2][8][4];
  #pragma unroll
  for (int u=0;u<2;u++)
    #pragma unroll
    for (int v=0;v<8;v++)
      #pragma unroll
      for (int w=0;w<4;w++) acc[u][v][w]=0.f;

  const int r = tid>>3, c4 = (tid&7)*4;
  for (int kb=0; kb<HID; kb+=32) {
    #pragma unroll
    for (int rr=r; rr<128; rr+=32) {
      float4 v = *reinterpret_cast<const float4*>(&x[(size_t)(m0+rr)*HID + kb + c4]);
      a_s[rr][c4]=f2tf(v.x); a_s[rr][c4+1]=f2tf(v.y);
      a_s[rr][c4+2]=f2tf(v.z); a_s[rr][c4+3]=f2tf(v.w);
    }
    #pragma unroll
    for (int rr=r; rr<128; rr+=32) {
      int j = (n0 + rr) & 1023;
      float4 v = *reinterpret_cast<const float4*>(&Wp[(size_t)j*2048 + kb + c4]);
      b_s[rr][c4]=f2tf(v.x); b_s[rr][c4+1]=f2tf(v.y);
      b_s[rr][c4+2]=f2tf(v.z); b_s[rr][c4+3]=f2tf(v.w);
    }
    __syncthreads();
    #pragma unroll
    for (int k8=0;k8<4;k8++){
      unsigned af[2][4], bfr[8][2];
      #pragma unroll
      for (int mt=0;mt<2;mt++){
        int row = wm*32 + mt*16;
        af[mt][0]=a_s[row+gid  ][k8*8+tig];
        af[mt][1]=a_s[row+gid+8][k8*8+tig];
        af[mt][2]=a_s[row+gid  ][k8*8+tig+4];
        af[mt][3]=a_s[row+gid+8][k8*8+tig+4];
      }
      #pragma unroll
      for (int nt=0;nt<8;nt++){
        int col = wn*64 + nt*8 + gid;
        bfr[nt][0]=b_s[col][k8*8+tig];
        bfr[nt][1]=b_s[col][k8*8+tig+4];
      }
      #pragma unroll
      for (int mt=0;mt<2;mt++)
        #pragma unroll
        for (int nt=0;nt<8;nt++)
          mma8(acc[mt][nt], af[mt], bfr[nt][0], bfr[nt][1]);
    }
    __syncthreads();
  }
  #pragma unroll
  for (int mt=0;mt<2;mt++){
    #pragma unroll
    for (int nt=0;nt<8;nt++){
      int row0 = m0 + wm*32 + mt*16 + gid;
      int col  = n0 + wn*64 + nt*8 + tig*2;
      int j = col & 1023;
      float b0v = bp[j], b1v = bp[j+1];
      int s0 = row0>>6,     bb0 = row0&63;
      int s1 = (row0+8)>>6, bb1 = (row0+8)&63;
      size_t base0 = (size_t)s0*((size_t)G4*BATCH) + (size_t)col*BATCH;
      size_t base1 = (size_t)s1*((size_t)G4*BATCH) + (size_t)col*BATCH;
      g_xz[base0 + bb0]         = acc[mt][nt][0] + b0v;
      g_xz[base0 + BATCH + bb0] = acc[mt][nt][1] + b1v;
      g_xz[base1 + bb1]         = acc[mt][nt][2] + b0v;
      g_xz[base1 + BATCH + bb1] = acc[mt][nt][3] + b1v;
    }
  }
}

// ---------------- phase 2 smem layout (byte offsets) -------------------------
#define OFF_WHV   0                      // 32 x 1024 u32 pre-arranged A-frags (131072 B)
#define OFF_HB    131072                 // 4 chunk buffers: 64 x 64 u32 (16384 B each)
#define OFF_ZBUF  196608                 // 32 x 65 f32 (8320 B)
#define OFF_ZH    204928                 // 8 x 65 f32  (2080 B)
#define OFF_CS    207008                 // 64 x 8 f32  (2048 B)
#define OFF_MBAR  209056                 // 4 x 8 B
#define SMEM2_BYTES 209088

#define NCHUNK 16      // 16 chunks of 64 k-rows per step
#define NBUF   4       // 4 buffers -> 3 chunks in flight ahead
#define CHUNK_WORDS 4096   // 64 k x 64 b
#define CHUNK_BYTES 16384

// ---------------- phase 2: persistent recurrent kernel -----------------------
// 128 CTAs (1/SM). CTA c owns hidden units j in [8c,8c+8): z^T[32 gate-j][64 b].
// A = Wh (smem, pre-arranged frags, LDS.128), B = h (bulk-copied 16KB k-chunks,
// swizzled [k][b], 4-buffer pipeline, depth 3), 8 warps = 2 m-halves x 4 n-qtrs.
__global__ void __launch_bounds__(256,1) lstm_steps_kernel(
    const float* __restrict__ x, const float* __restrict__ c0,
    const float* __restrict__ Wf,const float* __restrict__ Wi,
    const float* __restrict__ Wg,const float* __restrict__ Wo,
    float* __restrict__ out)
{
  extern __shared__ char smem[];
  uint4*    whv  = reinterpret_cast<uint4*>(smem + OFF_WHV);
  unsigned* whvw = reinterpret_cast<unsigned*>(smem + OFF_WHV);
  unsigned* hb[NBUF];
  unsigned  hb_sm[NBUF];
  #pragma unroll
  for (int b=0;b<NBUF;b++){
    hb[b]    = reinterpret_cast<unsigned*>(smem + OFF_HB + b*CHUNK_BYTES);
    hb_sm[b] = (unsigned)__cvta_generic_to_shared(smem + OFF_HB + b*CHUNK_BYTES);
  }
  float*    zbuf = reinterpret_cast<float*>(smem + OFF_ZBUF);   // stride 65
  float*    zh   = reinterpret_cast<float*>(smem + OFF_ZH);     // stride 65
  float*    cs   = reinterpret_cast<float*>(smem + OFF_CS);
  unsigned  mb_base = (unsigned)__cvta_generic_to_shared(smem + OFF_MBAR);

  const int tid = threadIdx.x, wid = tid>>5, lane = tid&31;
  const int gid = lane>>2, tig = lane&3;
  const int mh = wid&1, nq = wid>>1;      // m-half (16 of 32), n-quarter (16 of 64)
  const int cta = blockIdx.x, j0 = cta*8;

  // ---- prologue: fill pre-arranged Wh frags -------------------------------
  // A-frag for (mh,k8,lane): e0=A[mh16+gid][8k8+tig] e1=A[+8][tig] e2=A[gid][tig+4] e3=A[+8][tig+4]
  for (int c = 0; c < 32; c++){
    int gatec = c & 3, jl = c >> 2;
    const float* Wp = (gatec==0)?Wf:(gatec==1)?Wi:(gatec==2)?Wg:Wo;
    float4 v = *reinterpret_cast<const float4*>(&Wp[(size_t)(j0+jl)*2048 + 1024 + tid*4]);
    int cmh = c>>4, cgid = c&7, ihalf = (c>>3)&1;
    float vv[4] = {v.x, v.y, v.z, v.w};
    #pragma unroll
    for (int q=0;q<4;q++){
      int k = tid*4 + q;
      int k8 = k>>3, ktig = k&3, khalf = (k>>2)&1;
      int e = ihalf + (khalf<<1);
      whvw[(((cmh*128 + k8)*32) + (cgid*4 + ktig))*4 + e] = f2tf(vv[q]);
    }
  }
  for (int t = tid; t < 512; t += 256) {
    int b = t>>3, jl = t&7;
    cs[t] = c0[b*HID + j0 + jl];
  }
  if (tid == 0){
    #pragma unroll
    for (int b=0;b<NBUF;b++) mbar_init(mb_base + 8*b, 1);
  }
  __syncthreads();

  unsigned ph[NBUF] = {0u,0u,0u,0u};
  const size_t HSEQ = (size_t)S_LEN*BATCH*HID;

  // per-thread B-column constants (swizzle XOR folded into column index)
  const int bcol0 = nq*16 + gid;               // nt=0
  const int bcol1 = nq*16 + 8 + gid;           // nt=1
  const unsigned bx0 = (unsigned)bcol0 ^ (unsigned)(tig<<3) ^ (unsigned)(((bcol0>>5)&1)<<2);
  const unsigned bx1 = (unsigned)bcol1 ^ (unsigned)(tig<<3) ^ (unsigned)(((bcol1>>5)&1)<<2);

  // xz prefetch (for step 0)
  float2 px[4];
  #pragma unroll
  for (int i2=0;i2<4;i2++){
    int nt = i2>>1, ih = i2&1;
    int c = mh*16 + gid + ih*8;
    int bc = nq*16 + nt*8 + 2*tig;
    int gcol = (c&3)*HID + j0 + (c>>2);
    px[i2] = *reinterpret_cast<const float2*>(&g_xz[(size_t)gcol*BATCH + bc]);
  }

  for (int s=0; s<S_LEN; s++){
    const unsigned* hr = g_hT[s&1];

    // issue chunks 0..2 (h for this step is ready: gemm-init or previous barrier)
    if (tid == 0){
      asm volatile("fence.proxy.async;" ::: "memory");
      #pragma unroll
      for (int p=0;p<3;p++){
        mbar_expect_tx(mb_base + 8*p, CHUNK_BYTES);
        bulk_g2s(hb_sm[p], hr + p*CHUNK_WORDS, CHUNK_BYTES, mb_base + 8*p);
      }
    }

    // init accumulators from prefetched xz (bias already included)
    float acc[2][4];
    #pragma unroll
    for (int i2=0;i2<4;i2++){
      int nt = i2>>1, ih = i2&1;
      acc[nt][ih*2+0] = px[i2].x;
      acc[nt][ih*2+1] = px[i2].y;
    }

    // prefetch xz for next step (independent of recurrence)
    if (s < S_LEN-1){
      const size_t sbase = (size_t)(s+1) * ((size_t)G4*BATCH);
      #pragma unroll
      for (int i2=0;i2<4;i2++){
        int nt = i2>>1, ih = i2&1;
        int c = mh*16 + gid + ih*8;
        int bc = nq*16 + nt*8 + 2*tig;
        int gcol = (c&3)*HID + j0 + (c>>2);
        px[i2] = *reinterpret_cast<const float2*>(&g_xz[sbase + (size_t)gcol*BATCH + bc]);
      }
    }

    // ---- K loop: 16 chunks of 64 k, 4 buffers, 3 in flight ----------------
    #pragma unroll 1
    for (int ch=0; ch<NCHUNK; ch++){
      const int buf = ch & 3;
      __syncthreads();                 // all warps done with chunk ch-1 -> its buffer free
      if (ch < NCHUNK-3 && tid == 0){
        const int ib = (ch+3) & 3;     // == (ch-1)&3, freed by the sync above
        mbar_expect_tx(mb_base + 8*ib, CHUNK_BYTES);
        bulk_g2s(hb_sm[ib], hr + (ch+3)*CHUNK_WORDS, CHUNK_BYTES, mb_base + 8*ib);
      }
      mbar_wait(mb_base + 8*buf, ph[buf]);
      ph[buf] ^= 1u;

      const unsigned* hbp = hb[buf];
      #pragma unroll
      for (int k8l=0;k8l<8;k8l++){
        int kk = ch*8 + k8l;
        uint4 av = whv[(mh*128 + kk)*32 + lane];
        unsigned off0 = (unsigned)((k8l*8 + tig)*64);
        unsigned b00 = hbp[off0 + bx0];
        unsigned b01 = hbp[off0 + 256 + bx0];
        unsigned b10 = hbp[off0 + bx1];
        unsigned b11 = hbp[off0 + 256 + bx1];
        mma8(acc[0], reinterpret_cast<unsigned*>(&av), b00, b01);
        mma8(acc[1], reinterpret_cast<unsigned*>(&av), b10, b11);
      }
    }

    // ---- epilogue: z -> gates -> c,h --------------------------------------
    #pragma unroll
    for (int nt=0;nt<2;nt++){
      int bc = nq*16 + nt*8 + 2*tig;
      int cA = mh*16 + gid, cB = cA + 8;
      zbuf[cA*65 + bc]   = acc[nt][0];
      zbuf[cA*65 + bc+1] = acc[nt][1];
      zbuf[cB*65 + bc]   = acc[nt][2];
      zbuf[cB*65 + bc+1] = acc[nt][3];
    }
    __syncthreads();

    unsigned* hwv = g_hT[(s+1)&1];
    #pragma unroll
    for (int p=0;p<2;p++){
      int jl = tid & 7;
      int b  = (tid >> 3) + p*32;
      int cbase = jl*4;
      float zf = zbuf[(cbase+0)*65 + b];
      float zi = zbuf[(cbase+1)*65 + b];
      float zg = zbuf[(cbase+2)*65 + b];
      float zo = zbuf[(cbase+3)*65 + b];
      float fg = 1.f/(1.f+__expf(-zf));
      float ig = 1.f/(1.f+__expf(-zi));
      float gg = tanhf(zg);
      float og = 1.f/(1.f+__expf(-zo));
      float cc = fg*cs[b*8+jl] + ig*gg;
      float hh = og*tanhf(cc);
      cs[b*8+jl] = cc;
      int j = j0 + jl;
      size_t xi = ((size_t)(s*BATCH + b))*HID + j;
      out[xi] = x[xi] + hh;
      zh[jl*65 + b] = hh;
      if (s == S_LEN-1){
        out[HSEQ + (size_t)b*HID + j]                     = hh;   // h_f
        out[HSEQ + (size_t)BATCH*HID + (size_t)b*HID + j] = cc;   // c_f
      }
    }
    __syncthreads();

    // h write: [k=j][b], swizzled, coalesced (warp = fixed j, 32 consecutive b)
    #pragma unroll
    for (int p=0;p<2;p++){
      int jl = tid >> 5;
      int b  = (tid & 31) + p*32;
      hwv[hswz(j0+jl, b)] = f2tf(zh[jl*65 + b]);
    }

    // grid barrier (skip after last step)
    if (s < S_LEN-1){
      __syncthreads();
      if (tid == 0){
        __threadfence();
        atomicAdd(&g_bar, 1u);
        unsigned target = (unsigned)RGRID * (unsigned)(s+1);
        while (ld_acq(&g_bar) < target) { }
      }
      __syncthreads();
    }
  }
}

// ---------------- launch ------------------------------------------------------
extern "C" void kernel_launch(void* const* d_in, const int* in_sizes, int n_in,
                              void* d_out, int out_size) {
  const float* x   = (const float*)d_in[0];
  const float* h0  = (const float*)d_in[1];
  const float* c0  = (const float*)d_in[2];
  const float* Wf  = (const float*)d_in[3];
  const float* bf_ = (const float*)d_in[4];
  const float* Wi  = (const float*)d_in[5];
  const float* bi_ = (const float*)d_in[6];
  const float* Wg  = (const float*)d_in[7];
  const float* bg_ = (const float*)d_in[8];
  const float* Wo  = (const float*)d_in[9];
  const float* bo_ = (const float*)d_in[10];
  float* out = (float*)d_out;

  cudaFuncSetAttribute(lstm_steps_kernel,
                       cudaFuncAttributeMaxDynamicSharedMemorySize, SMEM2_BYTES);

  gemm_xz_kernel<<<dim3(32,128),256>>>(x, h0, Wf,Wi,Wg,Wo, bf_,bi_,bg_,bo_);
  lstm_steps_kernel<<<RGRID,256,SMEM2_BYTES>>>(x, c0, Wf,Wi,Wg,Wo, out);
}

// round 5
// speedup vs baseline: 1.4525x; 1.4525x over previous
#include <cuda_runtime.h>
#include <cstdint>

#define S_LEN 256
#define BATCH 64
#define HID   1024
#define G4    4096
#define RGRID 128

// ---------------- device scratch (no runtime allocation allowed) ------------
__device__ float    g_xz[(size_t)S_LEN * G4 * BATCH];  // 256 MB, layout [s][n][b]
__device__ unsigned g_hT[2][HID*BATCH];                // h ping-pong, tf32 bits, frag-packed
__device__ unsigned g_bar;                             // monotonic grid barrier

// ---------------- helpers ----------------------------------------------------
__device__ __forceinline__ unsigned f2tf(float x){
  unsigned u; asm("cvt.rna.tf32.f32 %0, %1;" : "=r"(u) : "f"(x)); return u;
}
__device__ __forceinline__ void mma8(float* d, const unsigned* a, unsigned b0, unsigned b1){
  asm volatile("mma.sync.aligned.m16n8k8.row.col.f32.tf32.tf32.f32 "
      "{%0,%1,%2,%3},{%4,%5,%6,%7},{%8,%9},{%0,%1,%2,%3};"
      : "+f"(d[0]),"+f"(d[1]),"+f"(d[2]),"+f"(d[3])
      : "r"(a[0]),"r"(a[1]),"r"(a[2]),"r"(a[3]),"r"(b0),"r"(b1));
}
__device__ __forceinline__ unsigned ld_acq(const unsigned* p){
  unsigned v; asm volatile("ld.acquire.gpu.global.u32 %0, [%1];" : "=r"(v) : "l"(p)); return v;
}
// frag-packed word index for h element B[k=j][n=b]:
// uint4 at (k8, p, lane) holds {B[8k8+tig][16p+gid], B[8k8+tig+4][16p+gid],
//                               B[8k8+tig][16p+8+gid], B[8k8+tig+4][16p+8+gid]}
__device__ __forceinline__ unsigned hW(unsigned j, unsigned b){
  return (j>>3)*512u + (b>>4)*128u + ((b&7u)*4u + (j&3u))*4u
       + ((j>>2)&1u) + 2u*((b>>3)&1u);
}

// ---------------- phase 1: xz = x @ Wx^T + b  (tf32 mma GEMM) + fused init ---
__global__ void __launch_bounds__(256,2) gemm_xz_kernel(
    const float* __restrict__ x, const float* __restrict__ h0,
    const float* __restrict__ Wf, const float* __restrict__ Wi,
    const float* __restrict__ Wg, const float* __restrict__ Wo,
    const float* __restrict__ bfp, const float* __restrict__ bip,
    const float* __restrict__ bgp, const float* __restrict__ bop)
{
  // fused init: block (0,0) resets barrier and writes h0 (tf32, frag-packed)
  if (blockIdx.x==0 && blockIdx.y==0) {
    if (threadIdx.x==0) g_bar = 0;
    for (int i = threadIdx.x; i < BATCH*HID; i += 256) {
      int b = i >> 10, j = i & 1023;
      g_hT[0][hW(j, b)] = f2tf(h0[i]);
    }
  }

  __shared__ unsigned a_s[128][36];
  __shared__ unsigned b_s[128][36];
  const int m0 = blockIdx.y*128, n0 = blockIdx.x*128;
  const int tid = threadIdx.x, wid = tid>>5, lane = tid&31;
  const int wm = wid&3, wn = wid>>2, gid = lane>>2, tig = lane&3;
  const int gate = n0 >> 10;
  const float* Wp = (gate==0)?Wf:(gate==1)?Wi:(gate==2)?Wg:Wo;
  const float* bp = (gate==0)?bfp:(gate==1)?bip:(gate==2)?bgp:bop;

  float acc[2][8][4];
  #pragma unroll
  for (int u=0;u<2;u++)
    #pragma unroll
    for (int v=0;v<8;v++)
      #pragma unroll
      for (int w=0;w<4;w++) acc[u][v][w]=0.f;

  const int r = tid>>3, c4 = (tid&7)*4;
  for (int kb=0; kb<HID; kb+=32) {
    #pragma unroll
    for (int rr=r; rr<128; rr+=32) {
      float4 v = *reinterpret_cast<const float4*>(&x[(size_t)(m0+rr)*HID + kb + c4]);
      a_s[rr][c4]=f2tf(v.x); a_s[rr][c4+1]=f2tf(v.y);
      a_s[rr][c4+2]=f2tf(v.z); a_s[rr][c4+3]=f2tf(v.w);
    }
    #pragma unroll
    for (int rr=r; rr<128; rr+=32) {
      int j = (n0 + rr) & 1023;
      float4 v = *reinterpret_cast<const float4*>(&Wp[(size_t)j*2048 + kb + c4]);
      b_s[rr][c4]=f2tf(v.x); b_s[rr][c4+1]=f2tf(v.y);
      b_s[rr][c4+2]=f2tf(v.z); b_s[rr][c4+3]=f2tf(v.w);
    }
    __syncthreads();
    #pragma unroll
    for (int k8=0;k8<4;k8++){
      unsigned af[2][4], bfr[8][2];
      #pragma unroll
      for (int mt=0;mt<2;mt++){
        int row = wm*32 + mt*16;
        af[mt][0]=a_s[row+gid  ][k8*8+tig];
        af[mt][1]=a_s[row+gid+8][k8*8+tig];
        af[mt][2]=a_s[row+gid  ][k8*8+tig+4];
        af[mt][3]=a_s[row+gid+8][k8*8+tig+4];
      }
      #pragma unroll
      for (int nt=0;nt<8;nt++){
        int col = wn*64 + nt*8 + gid;
        bfr[nt][0]=b_s[col][k8*8+tig];
        bfr[nt][1]=b_s[col][k8*8+tig+4];
      }
      #pragma unroll
      for (int mt=0;mt<2;mt++)
        #pragma unroll
        for (int nt=0;nt<8;nt++)
          mma8(acc[mt][nt], af[mt], bfr[nt][0], bfr[nt][1]);
    }
    __syncthreads();
  }
  #pragma unroll
  for (int mt=0;mt<2;mt++){
    #pragma unroll
    for (int nt=0;nt<8;nt++){
      int row0 = m0 + wm*32 + mt*16 + gid;
      int col  = n0 + wn*64 + nt*8 + tig*2;
      int j = col & 1023;
      float b0v = bp[j], b1v = bp[j+1];
      int s0 = row0>>6,     bb0 = row0&63;
      int s1 = (row0+8)>>6, bb1 = (row0+8)&63;
      size_t base0 = (size_t)s0*((size_t)G4*BATCH) + (size_t)col*BATCH;
      size_t base1 = (size_t)s1*((size_t)G4*BATCH) + (size_t)col*BATCH;
      g_xz[base0 + bb0]         = acc[mt][nt][0] + b0v;
      g_xz[base0 + BATCH + bb0] = acc[mt][nt][1] + b1v;
      g_xz[base1 + bb1]         = acc[mt][nt][2] + b0v;
      g_xz[base1 + BATCH + bb1] = acc[mt][nt][3] + b1v;
    }
  }
}

// ---------------- phase 2 smem layout (byte offsets) -------------------------
#define OFF_WHV   0          // 8192 uint4: A-frags, idx (k8*2+mt)*32+lane (131072 B)
#define OFF_RED   131072     // 8 x 2048 f32 partials, XOR-swizzled (65536 B)
#define OFF_ZBUF  196608     // 32 x 65 f32 (8320 B)
#define OFF_CS    204928     // 64 x 8 f32 (2048 B)
#define SMEM2_BYTES 206976

// ---------------- phase 2: persistent recurrent kernel -----------------------
// 128 CTAs (1/SM). CTA c owns hidden units j in [8c,8c+8): z^T[32 gate-j][64 b].
// K split across warps: warp w owns k8 in {w, w+8, ..., w+120}, computes the
// full 32x64 tile (acc[2][8][4]). A = Wh frag-packed in smem (LDS.128).
// B = h read straight from L2 via frag-packed LDG.128, depth-2 reg prefetch.
// Cross-warp reduction through smem, then gates + grid barrier.
__global__ void __launch_bounds__(256,1) lstm_steps_kernel(
    const float* __restrict__ x, const float* __restrict__ c0,
    const float* __restrict__ Wf,const float* __restrict__ Wi,
    const float* __restrict__ Wg,const float* __restrict__ Wo,
    float* __restrict__ out)
{
  extern __shared__ char smem[];
  uint4*    whv4 = reinterpret_cast<uint4*>(smem + OFF_WHV);
  unsigned* whvw = reinterpret_cast<unsigned*>(smem + OFF_WHV);
  float*    red  = reinterpret_cast<float*>(smem + OFF_RED);
  float*    zbuf = reinterpret_cast<float*>(smem + OFF_ZBUF);   // stride 65
  float*    cs   = reinterpret_cast<float*>(smem + OFF_CS);

  const int tid = threadIdx.x, wid = tid>>5, lane = tid&31;
  const int gid = lane>>2, tig = lane&3;
  const int cta = blockIdx.x, j0 = cta*8;

  // ---- prologue: pack Wh A-frags into smem --------------------------------
  // local z row c (0..31): gate = c&3, jl = c>>2. A[c][k] = Wh_gate[(j0+jl)][k].
  for (int c = 0; c < 32; c++){
    int gatec = c & 3, jl = c >> 2;
    const float* Wp = (gatec==0)?Wf:(gatec==1)?Wi:(gatec==2)?Wg:Wo;
    float4 v = *reinterpret_cast<const float4*>(&Wp[(size_t)(j0+jl)*2048 + 1024 + tid*4]);
    float vv[4] = {v.x, v.y, v.z, v.w};
    #pragma unroll
    for (int q=0;q<4;q++){
      int k = tid*4 + q;
      unsigned word = (unsigned)(((k>>3)*2 + (c>>4))*128
                    + ((c&7)*4 + (k&3))*4
                    + ((c>>3)&1) + 2*((k>>2)&1));
      whvw[word] = f2tf(vv[q]);
    }
  }
  for (int t = tid; t < 512; t += 256) {
    int b = t>>3, jl = t&7;
    cs[t] = c0[b*HID + j0 + jl];
  }
  __syncthreads();

  const size_t HSEQ = (size_t)S_LEN*BATCH*HID;
  // sum-phase coordinates for this thread
  const int sm_m  = tid>>3;              // z row c (0..31)
  const int sm_n0 = (tid&7)*8;           // batch block start
  const int sm_x  = (sm_m&3)<<3;         // XOR swizzle mask
  const int sm_gcol = (sm_m&3)*HID + j0 + (sm_m>>2);

  for (int s=0; s<S_LEN; s++){
    const uint4* hB = reinterpret_cast<const uint4*>(g_hT[s&1]);

    // xz prefetch for this step (consumed in sum phase; hidden under K-loop)
    float4 px0, px1;
    {
      const float* xp = &g_xz[(size_t)s*((size_t)G4*BATCH) + (size_t)sm_gcol*BATCH + sm_n0];
      px0 = *reinterpret_cast<const float4*>(xp);
      px1 = *reinterpret_cast<const float4*>(xp+4);
    }

    // ---- K loop: warp wid owns k8 = wid + 8t, t=0..15; depth-2 B prefetch ---
    float acc[2][8][4];
    #pragma unroll
    for (int u=0;u<2;u++)
      #pragma unroll
      for (int v=0;v<8;v++)
        #pragma unroll
        for (int q=0;q<4;q++) acc[u][v][q]=0.f;

    uint4 bA[4], bB[4];
    #pragma unroll
    for (int p=0;p<4;p++) bA[p] = hB[(unsigned)(wid*128 + p*32 + lane)];
    #pragma unroll
    for (int p=0;p<4;p++) bB[p] = hB[(unsigned)((wid+8)*128 + p*32 + lane)];

    #pragma unroll
    for (int tt=0; tt<8; tt++){
      const int k8a = wid + 16*tt;
      const int k8b = k8a + 8;
      // prefetch k8a+16 (guard: last iter reloads same, harmless)
      uint4 tA[4];
      {
        const int ka = (tt<7)? (k8a+16) : k8a;
        #pragma unroll
        for (int p=0;p<4;p++) tA[p] = hB[(unsigned)(ka*128 + p*32 + lane)];
      }
      {
        uint4 av0 = whv4[(k8a*2+0)*32 + lane];
        uint4 av1 = whv4[(k8a*2+1)*32 + lane];
        #pragma unroll
        for (int p=0;p<4;p++){
          mma8(acc[0][2*p],   reinterpret_cast<unsigned*>(&av0), bA[p].x, bA[p].y);
          mma8(acc[0][2*p+1], reinterpret_cast<unsigned*>(&av0), bA[p].z, bA[p].w);
          mma8(acc[1][2*p],   reinterpret_cast<unsigned*>(&av1), bA[p].x, bA[p].y);
          mma8(acc[1][2*p+1], reinterpret_cast<unsigned*>(&av1), bA[p].z, bA[p].w);
        }
      }
      #pragma unroll
      for (int p=0;p<4;p++) bA[p] = tA[p];
      // prefetch k8b+16
      uint4 tB[4];
      {
        const int kb = (tt<7)? (k8b+16) : k8b;
        #pragma unroll
        for (int p=0;p<4;p++) tB[p] = hB[(unsigned)(kb*128 + p*32 + lane)];
      }
      {
        uint4 av0 = whv4[(k8b*2+0)*32 + lane];
        uint4 av1 = whv4[(k8b*2+1)*32 + lane];
        #pragma unroll
        for (int p=0;p<4;p++){
          mma8(acc[0][2*p],   reinterpret_cast<unsigned*>(&av0), bB[p].x, bB[p].y);
          mma8(acc[0][2*p+1], reinterpret_cast<unsigned*>(&av0), bB[p].z, bB[p].w);
          mma8(acc[1][2*p],   reinterpret_cast<unsigned*>(&av1), bB[p].x, bB[p].y);
          mma8(acc[1][2*p+1], reinterpret_cast<unsigned*>(&av1), bB[p].z, bB[p].w);
        }
      }
      #pragma unroll
      for (int p=0;p<4;p++) bB[p] = tB[p];
    }

    // ---- store partials (XOR-swizzled, float2) -----------------------------
    #pragma unroll
    for (int mt=0;mt<2;mt++){
      #pragma unroll
      for (int nt=0;nt<8;nt++){
        int mr = mt*16 + gid;
        int n  = nt*8 + tig*2;
        int xn = n ^ ((mr&3)<<3);          // (mr+8)&3 == mr&3
        *reinterpret_cast<float2*>(&red[wid*2048 + mr*64 + xn])
            = make_float2(acc[mt][nt][0], acc[mt][nt][1]);
        *reinterpret_cast<float2*>(&red[wid*2048 + (mr+8)*64 + xn])
            = make_float2(acc[mt][nt][2], acc[mt][nt][3]);
      }
    }
    __syncthreads();

    // ---- sum across warps + xz --------------------------------------------
    float4 z0 = px0, z1 = px1;
    #pragma unroll
    for (int ww=0; ww<8; ww++){
      const float4* rp = reinterpret_cast<const float4*>(
          &red[ww*2048 + sm_m*64 + (sm_n0 ^ sm_x)]);
      float4 a0 = rp[0], a1 = rp[1];
      z0.x += a0.x; z0.y += a0.y; z0.z += a0.z; z0.w += a0.w;
      z1.x += a1.x; z1.y += a1.y; z1.z += a1.z; z1.w += a1.w;
    }
    zbuf[sm_m*65 + sm_n0 + 0] = z0.x;
    zbuf[sm_m*65 + sm_n0 + 1] = z0.y;
    zbuf[sm_m*65 + sm_n0 + 2] = z0.z;
    zbuf[sm_m*65 + sm_n0 + 3] = z0.w;
    zbuf[sm_m*65 + sm_n0 + 4] = z1.x;
    zbuf[sm_m*65 + sm_n0 + 5] = z1.y;
    zbuf[sm_m*65 + sm_n0 + 6] = z1.z;
    zbuf[sm_m*65 + sm_n0 + 7] = z1.w;
    __syncthreads();

    // ---- gates + state update + outputs ------------------------------------
    unsigned* hwv = g_hT[(s+1)&1];
    #pragma unroll
    for (int p=0;p<2;p++){
      int jl = tid & 7;
      int b  = (tid >> 3) + p*32;
      int cbase = jl*4;
      float zf = zbuf[(cbase+0)*65 + b];
      float zi = zbuf[(cbase+1)*65 + b];
      float zg = zbuf[(cbase+2)*65 + b];
      float zo = zbuf[(cbase+3)*65 + b];
      float fg = 1.f/(1.f+__expf(-zf));
      float ig = 1.f/(1.f+__expf(-zi));
      float gg = tanhf(zg);
      float og = 1.f/(1.f+__expf(-zo));
      float cc = fg*cs[b*8+jl] + ig*gg;
      float hh = og*tanhf(cc);
      cs[b*8+jl] = cc;
      int j = j0 + jl;
      size_t xi = ((size_t)(s*BATCH + b))*HID + j;
      out[xi] = x[xi] + hh;
      hwv[hW((unsigned)j, (unsigned)b)] = f2tf(hh);
      if (s == S_LEN-1){
        out[HSEQ + (size_t)b*HID + j]                     = hh;   // h_f
        out[HSEQ + (size_t)BATCH*HID + (size_t)b*HID + j] = cc;   // c_f
      }
    }

    // grid barrier (skip after last step)
    if (s < S_LEN-1){
      __syncthreads();
      if (tid == 0){
        __threadfence();
        atomicAdd(&g_bar, 1u);
        unsigned target = (unsigned)RGRID * (unsigned)(s+1);
        while (ld_acq(&g_bar) < target) { }
      }
      __syncthreads();
    }
  }
}

// ---------------- launch ------------------------------------------------------
extern "C" void kernel_launch(void* const* d_in, const int* in_sizes, int n_in,
                              void* d_out, int out_size) {
  const float* x   = (const float*)d_in[0];
  const float* h0  = (const float*)d_in[1];
  const float* c0  = (const float*)d_in[2];
  const float* Wf  = (const float*)d_in[3];
  const float* bf_ = (const float*)d_in[4];
  const float* Wi  = (const float*)d_in[5];
  const float* bi_ = (const float*)d_in[6];
  const float* Wg  = (const float*)d_in[7];
  const float* bg_ = (const float*)d_in[8];
  const float* Wo  = (const float*)d_in[9];
  const float* bo_ = (const float*)d_in[10];
  float* out = (float*)d_out;

  cudaFuncSetAttribute(lstm_steps_kernel,
                       cudaFuncAttributeMaxDynamicSharedMemorySize, SMEM2_BYTES);

  gemm_xz_kernel<<<dim3(32,128),256>>>(x, h0, Wf,Wi,Wg,Wo, bf_,bi_,bg_,bo_);
  lstm_steps_kernel<<<RGRID,256,SMEM2_BYTES>>>(x, c0, Wf,Wi,Wg,Wo, out);
}

// round 6
// speedup vs baseline: 1.6499x; 1.1360x over previous
#include <cuda_runtime.h>
#include <cstdint>

#define S_LEN 256
#define BATCH 64
#define HID   1024
#define G4    4096
#define RGRID 128

// ---------------- device scratch (no runtime allocation allowed) ------------
__device__ float    g_xz[(size_t)S_LEN * G4 * BATCH];  // 256 MB, layout [s][n][b]
__device__ unsigned g_hT[2][HID*BATCH];                // h ping-pong, tf32 bits, frag-packed
__device__ unsigned g_bar;                             // monotonic grid barrier

// ---------------- helpers ----------------------------------------------------
__device__ __forceinline__ unsigned f2tf(float x){
  unsigned u; asm("cvt.rna.tf32.f32 %0, %1;" : "=r"(u) : "f"(x)); return u;
}
__device__ __forceinline__ void mma8(float* d, const unsigned* a, unsigned b0, unsigned b1){
  asm volatile("mma.sync.aligned.m16n8k8.row.col.f32.tf32.tf32.f32 "
      "{%0,%1,%2,%3},{%4,%5,%6,%7},{%8,%9},{%0,%1,%2,%3};"
      : "+f"(d[0]),"+f"(d[1]),"+f"(d[2]),"+f"(d[3])
      : "r"(a[0]),"r"(a[1]),"r"(a[2]),"r"(a[3]),"r"(b0),"r"(b1));
}
__device__ __forceinline__ unsigned ld_acq(const unsigned* p){
  unsigned v; asm volatile("ld.acquire.gpu.global.u32 %0, [%1];" : "=r"(v) : "l"(p)); return v;
}
__device__ __forceinline__ uint4 ldcg4(const uint4* p){
  uint4 v;
  asm volatile("ld.global.cg.v4.u32 {%0,%1,%2,%3}, [%4];"
    : "=r"(v.x),"=r"(v.y),"=r"(v.z),"=r"(v.w) : "l"(p));
  return v;
}
// frag-packed word index for h element B[k=j][n=b]:
// uint4 at (k8, p, lane) holds {B[8k8+tig][16p+gid], B[8k8+tig+4][16p+gid],
//                               B[8k8+tig][16p+8+gid], B[8k8+tig+4][16p+8+gid]}
__device__ __forceinline__ unsigned hW(unsigned j, unsigned b){
  return (j>>3)*512u + (b>>4)*128u + ((b&7u)*4u + (j&3u))*4u
       + ((j>>2)&1u) + 2u*((b>>3)&1u);
}

// ---------------- phase 1: xz = x @ Wx^T + b  (tf32 mma GEMM) + fused init ---
__global__ void __launch_bounds__(256,2) gemm_xz_kernel(
    const float* __restrict__ x, const float* __restrict__ h0,
    const float* __restrict__ Wf, const float* __restrict__ Wi,
    const float* __restrict__ Wg, const float* __restrict__ Wo,
    const float* __restrict__ bfp, const float* __restrict__ bip,
    const float* __restrict__ bgp, const float* __restrict__ bop)
{
  // fused init: block (0,0) resets barrier and writes h0 (tf32, frag-packed)
  if (blockIdx.x==0 && blockIdx.y==0) {
    if (threadIdx.x==0) g_bar = 0;
    for (int i = threadIdx.x; i < BATCH*HID; i += 256) {
      int b = i >> 10, j = i & 1023;
      g_hT[0][hW(j, b)] = f2tf(h0[i]);
    }
  }

  __shared__ unsigned a_s[128][36];
  __shared__ unsigned b_s[128][36];
  const int m0 = blockIdx.y*128, n0 = blockIdx.x*128;
  const int tid = threadIdx.x, wid = tid>>5, lane = tid&31;
  const int wm = wid&3, wn = wid>>2, gid = lane>>2, tig = lane&3;
  const int gate = n0 >> 10;
  const float* Wp = (gate==0)?Wf:(gate==1)?Wi:(gate==2)?Wg:Wo;
  const float* bp = (gate==0)?bfp:(gate==1)?bip:(gate==2)?bgp:bop;

  float acc[2][8][4];
  #pragma unroll
  for (int u=0;u<2;u++)
    #pragma unroll
    for (int v=0;v<8;v++)
      #pragma unroll
      for (int w=0;w<4;w++) acc[u][v][w]=0.f;

  const int r = tid>>3, c4 = (tid&7)*4;
  for (int kb=0; kb<HID; kb+=32) {
    #pragma unroll
    for (int rr=r; rr<128; rr+=32) {
      float4 v = *reinterpret_cast<const float4*>(&x[(size_t)(m0+rr)*HID + kb + c4]);
      a_s[rr][c4]=f2tf(v.x); a_s[rr][c4+1]=f2tf(v.y);
      a_s[rr][c4+2]=f2tf(v.z); a_s[rr][c4+3]=f2tf(v.w);
    }
    #pragma unroll
    for (int rr=r; rr<128; rr+=32) {
      int j = (n0 + rr) & 1023;
      float4 v = *reinterpret_cast<const float4*>(&Wp[(size_t)j*2048 + kb + c4]);
      b_s[rr][c4]=f2tf(v.x); b_s[rr][c4+1]=f2tf(v.y);
      b_s[rr][c4+2]=f2tf(v.z); b_s[rr][c4+3]=f2tf(v.w);
    }
    __syncthreads();
    #pragma unroll
    for (int k8=0;k8<4;k8++){
      unsigned af[2][4], bfr[8][2];
      #pragma unroll
      for (int mt=0;mt<2;mt++){
        int row = wm*32 + mt*16;
        af[mt][0]=a_s[row+gid  ][k8*8+tig];
        af[mt][1]=a_s[row+gid+8][k8*8+tig];
        af[mt][2]=a_s[row+gid  ][k8*8+tig+4];
        af[mt][3]=a_s[row+gid+8][k8*8+tig+4];
      }
      #pragma unroll
      for (int nt=0;nt<8;nt++){
        int col = wn*64 + nt*8 + gid;
        bfr[nt][0]=b_s[col][k8*8+tig];
        bfr[nt][1]=b_s[col][k8*8+tig+4];
      }
      #pragma unroll
      for (int mt=0;mt<2;mt++)
        #pragma unroll
        for (int nt=0;nt<8;nt++)
          mma8(acc[mt][nt], af[mt], bfr[nt][0], bfr[nt][1]);
    }
    __syncthreads();
  }
  #pragma unroll
  for (int mt=0;mt<2;mt++){
    #pragma unroll
    for (int nt=0;nt<8;nt++){
      int row0 = m0 + wm*32 + mt*16 + gid;
      int col  = n0 + wn*64 + nt*8 + tig*2;
      int j = col & 1023;
      float b0v = bp[j], b1v = bp[j+1];
      int s0 = row0>>6,     bb0 = row0&63;
      int s1 = (row0+8)>>6, bb1 = (row0+8)&63;
      size_t base0 = (size_t)s0*((size_t)G4*BATCH) + (size_t)col*BATCH;
      size_t base1 = (size_t)s1*((size_t)G4*BATCH) + (size_t)col*BATCH;
      g_xz[base0 + bb0]         = acc[mt][nt][0] + b0v;
      g_xz[base0 + BATCH + bb0] = acc[mt][nt][1] + b1v;
      g_xz[base1 + bb1]         = acc[mt][nt][2] + b0v;
      g_xz[base1 + BATCH + bb1] = acc[mt][nt][3] + b1v;
    }
  }
}

// ---------------- phase 2 smem layout (byte offsets) -------------------------
#define OFF_WHV   0          // 8192 uint4: A-frags, idx (k8*2+mt)*32+lane (131072 B)
#define OFF_RED   131072     // 8 kw x (2 nh x 32 m x 32 b) f32, XOR-swizzled (65536 B)
#define OFF_ZBUF  196608     // 32 x 65 f32 (8320 B)
#define OFF_CS    204928     // 64 x 8 f32 (2048 B)
#define SMEM2_BYTES 206976

// ---------------- phase 2: persistent recurrent kernel -----------------------
// 128 CTAs (1/SM), 512 threads (16 warps). CTA c owns hidden units [8c,8c+8):
// z^T[32 gate-j][64 b]. Warp (kw = wid&7, nh = wid>>3): kw picks K-slice
// {kw,kw+8,...,kw+120}, nh picks a 32-batch half; acc[2][4][4].
// A = Wh frag-packed smem (LDS.128); B = h via L2 ld.global.cg.v4 (frag-packed),
// depth-2 register prefetch. Cross-warp reduction in smem, gates, grid barrier.
__global__ void __launch_bounds__(512,1) lstm_steps_kernel(
    const float* __restrict__ x, const float* __restrict__ c0,
    const float* __restrict__ Wf,const float* __restrict__ Wi,
    const float* __restrict__ Wg,const float* __restrict__ Wo,
    float* __restrict__ out)
{
  extern __shared__ char smem[];
  uint4*    whv4 = reinterpret_cast<uint4*>(smem + OFF_WHV);
  unsigned* whvw = reinterpret_cast<unsigned*>(smem + OFF_WHV);
  float*    red  = reinterpret_cast<float*>(smem + OFF_RED);
  float*    zbuf = reinterpret_cast<float*>(smem + OFF_ZBUF);   // stride 65
  float*    cs   = reinterpret_cast<float*>(smem + OFF_CS);

  const int tid = threadIdx.x, wid = tid>>5, lane = tid&31;
  const int gid = lane>>2, tig = lane&3;
  const int kw = wid & 7, nh = wid >> 3;
  const int cta = blockIdx.x, j0 = cta*8;

  // ---- prologue: pack Wh A-frags into smem (512 threads: 2 c-rows/pass) -----
  for (int cc = 0; cc < 16; cc++){
    int c = cc*2 + (tid>>8);           // local z row 0..31
    int gatec = c & 3, jl = c >> 2;
    const float* Wp = (gatec==0)?Wf:(gatec==1)?Wi:(gatec==2)?Wg:Wo;
    int kbase = (tid & 255)*4;
    float4 v = *reinterpret_cast<const float4*>(&Wp[(size_t)(j0+jl)*2048 + 1024 + kbase]);
    float vv[4] = {v.x, v.y, v.z, v.w};
    #pragma unroll
    for (int q=0;q<4;q++){
      int k = kbase + q;
      unsigned word = (unsigned)(((k>>3)*2 + (c>>4))*128
                    + ((c&7)*4 + (k&3))*4
                    + ((c>>3)&1) + 2*((k>>2)&1));
      whvw[word] = f2tf(vv[q]);
    }
  }
  {  // cs init: one element per thread (t = b*8 + jl)
    int b = tid>>3, jl = tid&7;
    cs[tid] = c0[b*HID + j0 + jl];
  }
  __syncthreads();

  const size_t HSEQ = (size_t)S_LEN*BATCH*HID;
  // sum-phase / xz coordinates
  const int sm_m  = tid>>4;                 // z row 0..31
  const int sm_nh = (tid>>3)&1;             // batch half
  const int sm_bq = tid&7;                  // float4 block in half
  const int sm_b  = sm_nh*32 + sm_bq*4;
  const int sm_gcol = (sm_m&3)*HID + j0 + (sm_m>>2);
  const int sm_rd = sm_nh*1024 + sm_m*32 + ((sm_bq ^ ((sm_m&3)<<1))<<2);
  // gate-phase coordinates
  const int gp_jl = tid & 7, gp_b = tid >> 3;
  // K-loop B indices
  const int p0 = nh*2;
  const unsigned bi0 = (unsigned)(p0*32 + lane);
  const unsigned bi1 = (unsigned)((p0+1)*32 + lane);

  for (int s=0; s<S_LEN; s++){
    const uint4* hB = reinterpret_cast<const uint4*>(g_hT[s&1]);

    // xz prefetch for this step (consumed in sum phase; hidden under K-loop)
    float4 px;
    px = *reinterpret_cast<const float4*>(
        &g_xz[(size_t)s*((size_t)G4*BATCH) + (size_t)sm_gcol*BATCH + sm_b]);

    // ---- K loop: k8 = kw + 8g, g=0..15; depth-2 register prefetch ----------
    float acc[2][4][4];
    #pragma unroll
    for (int u=0;u<2;u++)
      #pragma unroll
      for (int v=0;v<4;v++)
        #pragma unroll
        for (int q=0;q<4;q++) acc[u][v][q]=0.f;

    uint4 bq[2][2];
    bq[0][0] = ldcg4(hB + ((unsigned)kw*128u + bi0));
    bq[0][1] = ldcg4(hB + ((unsigned)kw*128u + bi1));
    bq[1][0] = ldcg4(hB + ((unsigned)(kw+8)*128u + bi0));
    bq[1][1] = ldcg4(hB + ((unsigned)(kw+8)*128u + bi1));

    #pragma unroll
    for (int g=0; g<16; g++){
      const int k8 = kw + 8*g;
      uint4 c0v = bq[g&1][0], c1v = bq[g&1][1];
      if (g < 14){
        bq[g&1][0] = ldcg4(hB + ((unsigned)(k8+16)*128u + bi0));
        bq[g&1][1] = ldcg4(hB + ((unsigned)(k8+16)*128u + bi1));
      }
      uint4 av0 = whv4[(k8*2+0)*32 + lane];
      uint4 av1 = whv4[(k8*2+1)*32 + lane];
      mma8(acc[0][0], reinterpret_cast<unsigned*>(&av0), c0v.x, c0v.y);
      mma8(acc[0][1], reinterpret_cast<unsigned*>(&av0), c0v.z, c0v.w);
      mma8(acc[0][2], reinterpret_cast<unsigned*>(&av0), c1v.x, c1v.y);
      mma8(acc[0][3], reinterpret_cast<unsigned*>(&av0), c1v.z, c1v.w);
      mma8(acc[1][0], reinterpret_cast<unsigned*>(&av1), c0v.x, c0v.y);
      mma8(acc[1][1], reinterpret_cast<unsigned*>(&av1), c0v.z, c0v.w);
      mma8(acc[1][2], reinterpret_cast<unsigned*>(&av1), c1v.x, c1v.y);
      mma8(acc[1][3], reinterpret_cast<unsigned*>(&av1), c1v.z, c1v.w);
    }

    // ---- store partials (XOR-swizzled float2) ------------------------------
    {
      float* rp = &red[kw*2048 + nh*1024];
      #pragma unroll
      for (int mt=0;mt<2;mt++){
        #pragma unroll
        for (int j=0;j<4;j++){
          int m  = mt*16 + gid;
          int bb = j*8 + 2*tig;
          int sw = (m&3)<<3;      // same for m and m+8
          *reinterpret_cast<float2*>(&rp[m*32 + (bb ^ sw)])
              = make_float2(acc[mt][j][0], acc[mt][j][1]);
          *reinterpret_cast<float2*>(&rp[(m+8)*32 + (bb ^ sw)])
              = make_float2(acc[mt][j][2], acc[mt][j][3]);
        }
      }
    }
    __syncthreads();

    // ---- sum across 8 kw + xz ----------------------------------------------
    {
      float4 z = px;
      #pragma unroll
      for (int w8=0; w8<8; w8++){
        float4 a = *reinterpret_cast<const float4*>(&red[w8*2048 + sm_rd]);
        z.x += a.x; z.y += a.y; z.z += a.z; z.w += a.w;
      }
      zbuf[sm_m*65 + sm_b + 0] = z.x;
      zbuf[sm_m*65 + sm_b + 1] = z.y;
      zbuf[sm_m*65 + sm_b + 2] = z.z;
      zbuf[sm_m*65 + sm_b + 3] = z.w;
    }
    __syncthreads();

    // ---- gates + state update + outputs ------------------------------------
    unsigned* hwv = g_hT[(s+1)&1];
    {
      int jl = gp_jl, b = gp_b;
      int cbase = jl*4;
      float zf = zbuf[(cbase+0)*65 + b];
      float zi = zbuf[(cbase+1)*65 + b];
      float zg = zbuf[(cbase+2)*65 + b];
      float zo = zbuf[(cbase+3)*65 + b];
      float fg = 1.f/(1.f+__expf(-zf));
      float ig = 1.f/(1.f+__expf(-zi));
      float gg = tanhf(zg);
      float og = 1.f/(1.f+__expf(-zo));
      float cc = fg*cs[tid] + ig*gg;
      float hh = og*tanhf(cc);
      cs[tid] = cc;
      int j = j0 + jl;
      size_t xi = ((size_t)(s*BATCH + b))*HID + j;
      out[xi] = x[xi] + hh;
      __stcg(&hwv[hW((unsigned)j, (unsigned)b)], f2tf(hh));
      if (s == S_LEN-1){
        out[HSEQ + (size_t)b*HID + j]                     = hh;   // h_f
        out[HSEQ + (size_t)BATCH*HID + (size_t)b*HID + j] = cc;   // c_f
      }
    }

    // grid barrier (skip after last step)
    if (s < S_LEN-1){
      __syncthreads();
      if (tid == 0){
        __threadfence();
        atomicAdd(&g_bar, 1u);
        unsigned target = (unsigned)RGRID * (unsigned)(s+1);
        while (ld_acq(&g_bar) < target) { }
      }
      __syncthreads();
    }
  }
}

// ---------------- launch ------------------------------------------------------
extern "C" void kernel_launch(void* const* d_in, const int* in_sizes, int n_in,
                              void* d_out, int out_size) {
  const float* x   = (const float*)d_in[0];
  const float* h0  = (const float*)d_in[1];
  const float* c0  = (const float*)d_in[2];
  const float* Wf  = (const float*)d_in[3];
  const float* bf_ = (const float*)d_in[4];
  const float* Wi  = (const float*)d_in[5];
  const float* bi_ = (const float*)d_in[6];
  const float* Wg  = (const float*)d_in[7];
  const float* bg_ = (const float*)d_in[8];
  const float* Wo  = (const float*)d_in[9];
  const float* bo_ = (const float*)d_in[10];
  float* out = (float*)d_out;

  cudaFuncSetAttribute(lstm_steps_kernel,
                       cudaFuncAttributeMaxDynamicSharedMemorySize, SMEM2_BYTES);

  gemm_xz_kernel<<<dim3(32,128),256>>>(x, h0, Wf,Wi,Wg,Wo, bf_,bi_,bg_,bo_);
  lstm_steps_kernel<<<RGRID,512,SMEM2_BYTES>>>(x, c0, Wf,Wi,Wg,Wo, out);
}